// round 1
// baseline (speedup 1.0000x reference)
#include <cuda_runtime.h>

#define T_SEQ   2048
#define D_MODEL 1024
#define N_HEADS 16
#define D_HEAD  64
#define B_SZ    2
#define N_TOK   (B_SZ * T_SEQ)   // 4096

// Scratch (device globals: allocation-free per harness rules)
__device__ float g_qkv[(size_t)N_TOK * 3 * D_MODEL];   // [4096, 3072]
__device__ float g_attn[(size_t)N_TOK * D_MODEL];      // [4096, 1024]

// ---------------------------------------------------------------------------
// Classic 128x128x8 register-blocked SGEMM with fused bias.
// C[M,N] = A[M,K] @ B[K,N] + bias[N], all row-major. M%128==0, N%128==0, K%8==0.
// 256 threads, each computes an 8x8 micro-tile.
// ---------------------------------------------------------------------------
template <int M, int N, int K>
__global__ void __launch_bounds__(256, 2) sgemm_bias_kernel(
    const float* __restrict__ A, const float* __restrict__ B,
    const float* __restrict__ bias, float* __restrict__ C)
{
    __shared__ float As[8 * 128];   // transposed: As[k][m]
    __shared__ float Bs[8 * 128];   // Bs[k][n]

    const int tid  = threadIdx.x;
    const int trow = tid >> 4;      // 0..15
    const int tcol = tid & 15;      // 0..15
    const int bm   = blockIdx.y;
    const int bn   = blockIdx.x;

    const float* Ab = A + (size_t)bm * 128 * K;
    const float* Bb = B + (size_t)bn * 128;

    const int ar = tid >> 1;          // 0..127 (A tile row)
    const int ac = (tid & 1) * 4;     // 0 or 4 (A tile col, float4)
    const int bk = tid >> 5;          // 0..7   (B tile row)
    const int bc = (tid & 31) * 4;    // 0..124 (B tile col, float4)

    float acc[8][8];
    #pragma unroll
    for (int i = 0; i < 8; ++i)
        #pragma unroll
        for (int j = 0; j < 8; ++j) acc[i][j] = 0.0f;

    for (int kt = 0; kt < K; kt += 8) {
        float4 av = *(const float4*)(Ab + (size_t)ar * K + kt + ac);
        float4 bv = *(const float4*)(Bb + (size_t)(kt + bk) * N + bc);
        As[(ac + 0) * 128 + ar] = av.x;
        As[(ac + 1) * 128 + ar] = av.y;
        As[(ac + 2) * 128 + ar] = av.z;
        As[(ac + 3) * 128 + ar] = av.w;
        *(float4*)(Bs + bk * 128 + bc) = bv;
        __syncthreads();

        #pragma unroll
        for (int k = 0; k < 8; ++k) {
            float a[8], b[8];
            *(float4*)(a)     = *(const float4*)(As + k * 128 + trow * 8);
            *(float4*)(a + 4) = *(const float4*)(As + k * 128 + trow * 8 + 4);
            *(float4*)(b)     = *(const float4*)(Bs + k * 128 + tcol * 8);
            *(float4*)(b + 4) = *(const float4*)(Bs + k * 128 + tcol * 8 + 4);
            #pragma unroll
            for (int i = 0; i < 8; ++i)
                #pragma unroll
                for (int j = 0; j < 8; ++j)
                    acc[i][j] = fmaf(a[i], b[j], acc[i][j]);
        }
        __syncthreads();
    }

    float bj[8];
    #pragma unroll
    for (int j = 0; j < 8; ++j) bj[j] = bias[bn * 128 + tcol * 8 + j];

    #pragma unroll
    for (int i = 0; i < 8; ++i) {
        float* crow = C + (size_t)(bm * 128 + trow * 8 + i) * N + bn * 128 + tcol * 8;
        float4 v0 = make_float4(acc[i][0] + bj[0], acc[i][1] + bj[1],
                                acc[i][2] + bj[2], acc[i][3] + bj[3]);
        float4 v1 = make_float4(acc[i][4] + bj[4], acc[i][5] + bj[5],
                                acc[i][6] + bj[6], acc[i][7] + bj[7]);
        *(float4*)(crow)     = v0;
        *(float4*)(crow + 4) = v1;
    }
}

// ---------------------------------------------------------------------------
// Causal flash attention, fp32, online softmax.
// Q tile: 64 rows; K/V tiles: 32 rows; DH = 64. 256 threads (16x16 grid).
// Reads g_qkv [4096, 3072] (Q|K|V blocks of 1024 cols, head h at col h*64).
// Writes g_attn in [B, T, H*DH] layout (directly usable by the out-proj GEMM).
// ---------------------------------------------------------------------------
__global__ void __launch_bounds__(256) flash_attn_kernel()
{
    __shared__ float Qs[64 * 65];
    __shared__ float Ks[32 * 65];
    __shared__ float Vs[32 * 65];
    __shared__ float Ps[64 * 33];

    const int tid = threadIdx.x;
    const int ty  = tid >> 4;     // 0..15 -> owns q-rows ty*4..ty*4+3
    const int tx  = tid & 15;     // 0..15
    const int qt  = blockIdx.x;
    const int h   = blockIdx.y;
    const int b   = blockIdx.z;
    const int q0  = qt * 64;

    const float* qkv = g_qkv;

    // Load Q tile (64x64) into smem, stride 65 (conflict-free)
    #pragma unroll
    for (int p = 0; p < 4; ++p) {
        int idx = tid + p * 256;          // 0..1023
        int r = idx >> 4;
        int c = (idx & 15) * 4;
        float4 v = *(const float4*)(qkv + (size_t)(b * T_SEQ + q0 + r) * 3072 + h * 64 + c);
        Qs[r * 65 + c + 0] = v.x;
        Qs[r * 65 + c + 1] = v.y;
        Qs[r * 65 + c + 2] = v.z;
        Qs[r * 65 + c + 3] = v.w;
    }

    float o[4][4];
    float mrow[4], lrow[4];
    #pragma unroll
    for (int i = 0; i < 4; ++i) {
        mrow[i] = -1e30f;
        lrow[i] = 0.0f;
        #pragma unroll
        for (int j = 0; j < 4; ++j) o[i][j] = 0.0f;
    }

    const int nkt = 2 * qt + 2;   // causal: k tiles cover [0, q0+64)

    for (int kt = 0; kt < nkt; ++kt) {
        const int k0 = kt * 32;

        __syncthreads();   // previous iteration's smem reads complete (and Q visible on iter 0)

        // Load K,V tiles (32x64 each)
        #pragma unroll
        for (int p = 0; p < 2; ++p) {
            int idx = tid + p * 256;      // 0..511
            int r = idx >> 4;
            int c = (idx & 15) * 4;
            const float* base = qkv + (size_t)(b * T_SEQ + k0 + r) * 3072 + h * 64 + c;
            float4 kv = *(const float4*)(base + 1024);
            float4 vv = *(const float4*)(base + 2048);
            Ks[r * 65 + c + 0] = kv.x; Ks[r * 65 + c + 1] = kv.y;
            Ks[r * 65 + c + 2] = kv.z; Ks[r * 65 + c + 3] = kv.w;
            Vs[r * 65 + c + 0] = vv.x; Vs[r * 65 + c + 1] = vv.y;
            Vs[r * 65 + c + 2] = vv.z; Vs[r * 65 + c + 3] = vv.w;
        }
        __syncthreads();

        // S = Q @ K^T   (64x32 tile; this thread: 4 rows x 2 cols)
        float s[4][2];
        #pragma unroll
        for (int i = 0; i < 4; ++i) { s[i][0] = 0.0f; s[i][1] = 0.0f; }

        #pragma unroll 8
        for (int d = 0; d < 64; ++d) {
            float qa[4], kb[2];
            #pragma unroll
            for (int i = 0; i < 4; ++i) qa[i] = Qs[(ty * 4 + i) * 65 + d];
            kb[0] = Ks[(tx * 2 + 0) * 65 + d];
            kb[1] = Ks[(tx * 2 + 1) * 65 + d];
            #pragma unroll
            for (int i = 0; i < 4; ++i) {
                s[i][0] = fmaf(qa[i], kb[0], s[i][0]);
                s[i][1] = fmaf(qa[i], kb[1], s[i][1]);
            }
        }

        // scale + causal mask (only the last two tiles straddle the diagonal)
        const bool domask = (k0 + 31 > q0);
        #pragma unroll
        for (int i = 0; i < 4; ++i)
            #pragma unroll
            for (int j = 0; j < 2; ++j) {
                float v = s[i][j] * 0.125f;   // 1/sqrt(64)
                if (domask && (k0 + tx * 2 + j > q0 + ty * 4 + i)) v = -1e30f;
                s[i][j] = v;
            }

        // online softmax (row stats across 16 tx lanes, width-16 shuffles)
        float pv[4][2];
        float alpha[4];
        #pragma unroll
        for (int i = 0; i < 4; ++i) {
            float mx = fmaxf(s[i][0], s[i][1]);
            #pragma unroll
            for (int off = 8; off >= 1; off >>= 1)
                mx = fmaxf(mx, __shfl_xor_sync(0xffffffffu, mx, off, 16));
            float nm = fmaxf(mrow[i], mx);
            alpha[i] = __expf(mrow[i] - nm);
            mrow[i]  = nm;
            pv[i][0] = __expf(s[i][0] - nm);
            pv[i][1] = __expf(s[i][1] - nm);
            float sm = pv[i][0] + pv[i][1];
            #pragma unroll
            for (int off = 8; off >= 1; off >>= 1)
                sm += __shfl_xor_sync(0xffffffffu, sm, off, 16);
            lrow[i] = lrow[i] * alpha[i] + sm;
        }

        #pragma unroll
        for (int i = 0; i < 4; ++i)
            #pragma unroll
            for (int j = 0; j < 4; ++j) o[i][j] *= alpha[i];

        // stage P to smem (stride 33), then O += P @ V
        #pragma unroll
        for (int i = 0; i < 4; ++i) {
            Ps[(ty * 4 + i) * 33 + tx * 2 + 0] = pv[i][0];
            Ps[(ty * 4 + i) * 33 + tx * 2 + 1] = pv[i][1];
        }
        __syncthreads();

        #pragma unroll 8
        for (int jj = 0; jj < 32; ++jj) {
            float pa[4], vb[4];
            #pragma unroll
            for (int i = 0; i < 4; ++i) pa[i] = Ps[(ty * 4 + i) * 33 + jj];
            #pragma unroll
            for (int j = 0; j < 4; ++j) vb[j] = Vs[jj * 65 + tx * 4 + j];
            #pragma unroll
            for (int i = 0; i < 4; ++i)
                #pragma unroll
                for (int j = 0; j < 4; ++j)
                    o[i][j] = fmaf(pa[i], vb[j], o[i][j]);
        }
    }

    // epilogue: normalize and write [B, T, H*DH]
    #pragma unroll
    for (int i = 0; i < 4; ++i) {
        float inv = 1.0f / lrow[i];
        float* orow = g_attn + (size_t)(b * T_SEQ + q0 + ty * 4 + i) * D_MODEL + h * 64 + tx * 4;
        float4 v = make_float4(o[i][0] * inv, o[i][1] * inv, o[i][2] * inv, o[i][3] * inv);
        *(float4*)orow = v;
    }
}

// ---------------------------------------------------------------------------
// Harness entry. Inputs: x, w_qkv, b_qkv, w_out, b_out (all fp32).
// ---------------------------------------------------------------------------
extern "C" void kernel_launch(void* const* d_in, const int* in_sizes, int n_in,
                              void* d_out, int out_size)
{
    (void)in_sizes; (void)n_in; (void)out_size;
    const float* x     = (const float*)d_in[0];
    const float* w_qkv = (const float*)d_in[1];
    const float* b_qkv = (const float*)d_in[2];
    const float* w_out = (const float*)d_in[3];
    const float* b_out = (const float*)d_in[4];
    float* out = (float*)d_out;

    float* qkv_buf  = nullptr;
    float* attn_buf = nullptr;
    cudaGetSymbolAddress((void**)&qkv_buf, g_qkv);
    cudaGetSymbolAddress((void**)&attn_buf, g_attn);

    // 1) QKV projection: [4096,1024] @ [1024,3072] + b
    sgemm_bias_kernel<N_TOK, 3 * D_MODEL, D_MODEL>
        <<<dim3((3 * D_MODEL) / 128, N_TOK / 128), 256>>>(x, w_qkv, b_qkv, qkv_buf);

    // 2) causal flash attention -> [B, T, H*DH]
    flash_attn_kernel<<<dim3(T_SEQ / 64, N_HEADS, B_SZ), 256>>>();

    // 3) output projection: [4096,1024] @ [1024,1024] + b
    sgemm_bias_kernel<N_TOK, D_MODEL, D_MODEL>
        <<<dim3(D_MODEL / 128, N_TOK / 128), 256>>>(attn_buf, w_out, b_out, out);
}

// round 3
// speedup vs baseline: 1.5947x; 1.5947x over previous
#include <cuda_runtime.h>
#include <cstdint>

#define T_SEQ   2048
#define D_MODEL 1024
#define N_HEADS 16
#define D_HEAD  64
#define B_SZ    2
#define N_TOK   (B_SZ * T_SEQ)   // 4096

// Scratch (device globals: allocation-free per harness rules)
__device__ float g_qkv[(size_t)N_TOK * 3 * D_MODEL];   // [4096, 3072]
__device__ float g_attn[(size_t)N_TOK * D_MODEL];      // [4096, 1024]

// ---------------------------------------------------------------------------
// tf32 helpers
// ---------------------------------------------------------------------------
__device__ __forceinline__ uint32_t f2tf32(float x) {
    uint32_t r;
    asm("cvt.rna.tf32.f32 %0, %1;" : "=r"(r) : "f"(x));
    return r;
}

__device__ __forceinline__ void mma_tf32(float c[4], const uint32_t a[4], const uint32_t b[2]) {
    asm volatile(
        "mma.sync.aligned.m16n8k8.row.col.f32.tf32.tf32.f32 "
        "{%0,%1,%2,%3}, {%4,%5,%6,%7}, {%8,%9}, {%0,%1,%2,%3};\n"
        : "+f"(c[0]), "+f"(c[1]), "+f"(c[2]), "+f"(c[3])
        : "r"(a[0]), "r"(a[1]), "r"(a[2]), "r"(a[3]), "r"(b[0]), "r"(b[1]));
}

// ---------------------------------------------------------------------------
// tf32 tensor-core GEMM with fused bias.
// C[M,N] = A[M,K] @ B[K,N] + bias[N], row-major. M%128==0, N%128==0, K%16==0.
// Block tile 128x128, K-tile 16. 128 threads = 4 warps, each warp 64x64.
// smem pads: ldA=20, ldB=136 -> both fragment read patterns bank-conflict-free.
// ---------------------------------------------------------------------------
#define LDA 20
#define LDB 136

template <int M, int N, int K>
__global__ void __launch_bounds__(128, 2) gemm_tf32_bias_kernel(
    const float* __restrict__ A, const float* __restrict__ B,
    const float* __restrict__ bias, float* __restrict__ C)
{
    __shared__ uint32_t As[128 * LDA];   // [128][16] padded
    __shared__ uint32_t Bs[16 * LDB];    // [16][128] padded

    const int tid  = threadIdx.x;
    const int warp = tid >> 5;
    const int lane = tid & 31;
    const int g    = lane >> 2;     // group id 0..7
    const int tg   = lane & 3;      // thread-in-group 0..3
    const int wm   = (warp >> 1) * 64;   // warp M offset: 0 or 64
    const int wn   = (warp & 1) * 64;    // warp N offset: 0 or 64

    const int bm = blockIdx.y;
    const int bn = blockIdx.x;

    const float* Ab = A + (size_t)bm * 128 * K;
    const float* Bb = B + (size_t)bn * 128;

    float acc[4][8][4];
    #pragma unroll
    for (int i = 0; i < 4; ++i)
        #pragma unroll
        for (int j = 0; j < 8; ++j)
            #pragma unroll
            for (int q = 0; q < 4; ++q) acc[i][j][q] = 0.0f;

    for (int kt = 0; kt < K; kt += 16) {
        // Prefetch gmem tiles into registers (overlaps previous compute)
        float4 areg[4], breg[4];
        #pragma unroll
        for (int p = 0; p < 4; ++p) {
            int f  = tid + p * 128;          // 0..511 float4 index
            int ar = f >> 2, ac = (f & 3) * 4;
            areg[p] = *(const float4*)(Ab + (size_t)ar * K + kt + ac);
            int br = f >> 5, bc = (f & 31) * 4;
            breg[p] = *(const float4*)(Bb + (size_t)(kt + br) * N + bc);
        }

        __syncthreads();   // previous iteration's smem reads done

        #pragma unroll
        for (int p = 0; p < 4; ++p) {
            int f  = tid + p * 128;
            int ar = f >> 2, ac = (f & 3) * 4;
            uint4 av = make_uint4(f2tf32(areg[p].x), f2tf32(areg[p].y),
                                  f2tf32(areg[p].z), f2tf32(areg[p].w));
            *(uint4*)(As + ar * LDA + ac) = av;
            int br = f >> 5, bc = (f & 31) * 4;
            uint4 bv = make_uint4(f2tf32(breg[p].x), f2tf32(breg[p].y),
                                  f2tf32(breg[p].z), f2tf32(breg[p].w));
            *(uint4*)(Bs + br * LDB + bc) = bv;
        }
        __syncthreads();

        #pragma unroll
        for (int ks = 0; ks < 2; ++ks) {
            const int kk = ks * 8;
            uint32_t a[4][4], b[8][2];
            #pragma unroll
            for (int mm = 0; mm < 4; ++mm) {
                const int r0 = wm + mm * 16;
                a[mm][0] = As[(r0 + g)     * LDA + kk + tg];
                a[mm][1] = As[(r0 + g + 8) * LDA + kk + tg];
                a[mm][2] = As[(r0 + g)     * LDA + kk + tg + 4];
                a[mm][3] = As[(r0 + g + 8) * LDA + kk + tg + 4];
            }
            #pragma unroll
            for (int nn = 0; nn < 8; ++nn) {
                const int c0 = wn + nn * 8 + g;
                b[nn][0] = Bs[(kk + tg)     * LDB + c0];
                b[nn][1] = Bs[(kk + tg + 4) * LDB + c0];
            }
            #pragma unroll
            for (int mm = 0; mm < 4; ++mm)
                #pragma unroll
                for (int nn = 0; nn < 8; ++nn)
                    mma_tf32(acc[mm][nn], a[mm], b[nn]);
        }
    }

    // Epilogue: bias + store.  c0,c1 at (row, col..col+1); c2,c3 at (row+8, ..).
    #pragma unroll
    for (int mm = 0; mm < 4; ++mm) {
        const int r0 = bm * 128 + wm + mm * 16 + g;
        #pragma unroll
        for (int nn = 0; nn < 8; ++nn) {
            const int c0g = bn * 128 + wn + nn * 8 + 2 * tg;
            float b0 = bias[c0g], b1 = bias[c0g + 1];
            float2 v0 = make_float2(acc[mm][nn][0] + b0, acc[mm][nn][1] + b1);
            float2 v1 = make_float2(acc[mm][nn][2] + b0, acc[mm][nn][3] + b1);
            *(float2*)(C + (size_t)r0 * N + c0g)       = v0;
            *(float2*)(C + (size_t)(r0 + 8) * N + c0g) = v1;
        }
    }
}

// ---------------------------------------------------------------------------
// Causal flash attention, fp32, online softmax (unchanged from round 1).
// ---------------------------------------------------------------------------
__global__ void __launch_bounds__(256) flash_attn_kernel()
{
    __shared__ float Qs[64 * 65];
    __shared__ float Ks[32 * 65];
    __shared__ float Vs[32 * 65];
    __shared__ float Ps[64 * 33];

    const int tid = threadIdx.x;
    const int ty  = tid >> 4;
    const int tx  = tid & 15;
    const int qt  = blockIdx.x;
    const int h   = blockIdx.y;
    const int b   = blockIdx.z;
    const int q0  = qt * 64;

    const float* qkv = g_qkv;

    #pragma unroll
    for (int p = 0; p < 4; ++p) {
        int idx = tid + p * 256;
        int r = idx >> 4;
        int c = (idx & 15) * 4;
        float4 v = *(const float4*)(qkv + (size_t)(b * T_SEQ + q0 + r) * 3072 + h * 64 + c);
        Qs[r * 65 + c + 0] = v.x;
        Qs[r * 65 + c + 1] = v.y;
        Qs[r * 65 + c + 2] = v.z;
        Qs[r * 65 + c + 3] = v.w;
    }

    float o[4][4];
    float mrow[4], lrow[4];
    #pragma unroll
    for (int i = 0; i < 4; ++i) {
        mrow[i] = -1e30f;
        lrow[i] = 0.0f;
        #pragma unroll
        for (int j = 0; j < 4; ++j) o[i][j] = 0.0f;
    }

    const int nkt = 2 * qt + 2;

    for (int kt = 0; kt < nkt; ++kt) {
        const int k0 = kt * 32;

        __syncthreads();

        #pragma unroll
        for (int p = 0; p < 2; ++p) {
            int idx = tid + p * 256;
            int r = idx >> 4;
            int c = (idx & 15) * 4;
            const float* base = qkv + (size_t)(b * T_SEQ + k0 + r) * 3072 + h * 64 + c;
            float4 kv = *(const float4*)(base + 1024);
            float4 vv = *(const float4*)(base + 2048);
            Ks[r * 65 + c + 0] = kv.x; Ks[r * 65 + c + 1] = kv.y;
            Ks[r * 65 + c + 2] = kv.z; Ks[r * 65 + c + 3] = kv.w;
            Vs[r * 65 + c + 0] = vv.x; Vs[r * 65 + c + 1] = vv.y;
            Vs[r * 65 + c + 2] = vv.z; Vs[r * 65 + c + 3] = vv.w;
        }
        __syncthreads();

        float s[4][2];
        #pragma unroll
        for (int i = 0; i < 4; ++i) { s[i][0] = 0.0f; s[i][1] = 0.0f; }

        #pragma unroll 8
        for (int d = 0; d < 64; ++d) {
            float qa[4], kb[2];
            #pragma unroll
            for (int i = 0; i < 4; ++i) qa[i] = Qs[(ty * 4 + i) * 65 + d];
            kb[0] = Ks[(tx * 2 + 0) * 65 + d];
            kb[1] = Ks[(tx * 2 + 1) * 65 + d];
            #pragma unroll
            for (int i = 0; i < 4; ++i) {
                s[i][0] = fmaf(qa[i], kb[0], s[i][0]);
                s[i][1] = fmaf(qa[i], kb[1], s[i][1]);
            }
        }

        const bool domask = (k0 + 31 > q0);
        #pragma unroll
        for (int i = 0; i < 4; ++i)
            #pragma unroll
            for (int j = 0; j < 2; ++j) {
                float v = s[i][j] * 0.125f;
                if (domask && (k0 + tx * 2 + j > q0 + ty * 4 + i)) v = -1e30f;
                s[i][j] = v;
            }

        float pv[4][2];
        float alpha[4];
        #pragma unroll
        for (int i = 0; i < 4; ++i) {
            float mx = fmaxf(s[i][0], s[i][1]);
            #pragma unroll
            for (int off = 8; off >= 1; off >>= 1)
                mx = fmaxf(mx, __shfl_xor_sync(0xffffffffu, mx, off, 16));
            float nm = fmaxf(mrow[i], mx);
            alpha[i] = __expf(mrow[i] - nm);
            mrow[i]  = nm;
            pv[i][0] = __expf(s[i][0] - nm);
            pv[i][1] = __expf(s[i][1] - nm);
            float sm = pv[i][0] + pv[i][1];
            #pragma unroll
            for (int off = 8; off >= 1; off >>= 1)
                sm += __shfl_xor_sync(0xffffffffu, sm, off, 16);
            lrow[i] = lrow[i] * alpha[i] + sm;
        }

        #pragma unroll
        for (int i = 0; i < 4; ++i)
            #pragma unroll
            for (int j = 0; j < 4; ++j) o[i][j] *= alpha[i];

        #pragma unroll
        for (int i = 0; i < 4; ++i) {
            Ps[(ty * 4 + i) * 33 + tx * 2 + 0] = pv[i][0];
            Ps[(ty * 4 + i) * 33 + tx * 2 + 1] = pv[i][1];
        }
        __syncthreads();

        #pragma unroll 8
        for (int jj = 0; jj < 32; ++jj) {
            float pa[4], vb[4];
            #pragma unroll
            for (int i = 0; i < 4; ++i) pa[i] = Ps[(ty * 4 + i) * 33 + jj];
            #pragma unroll
            for (int j = 0; j < 4; ++j) vb[j] = Vs[jj * 65 + tx * 4 + j];
            #pragma unroll
            for (int i = 0; i < 4; ++i)
                #pragma unroll
                for (int j = 0; j < 4; ++j)
                    o[i][j] = fmaf(pa[i], vb[j], o[i][j]);
        }
    }

    #pragma unroll
    for (int i = 0; i < 4; ++i) {
        float inv = 1.0f / lrow[i];
        float* orow = g_attn + (size_t)(b * T_SEQ + q0 + ty * 4 + i) * D_MODEL + h * 64 + tx * 4;
        float4 v = make_float4(o[i][0] * inv, o[i][1] * inv, o[i][2] * inv, o[i][3] * inv);
        *(float4*)orow = v;
    }
}

// ---------------------------------------------------------------------------
// Harness entry. Inputs: x, w_qkv, b_qkv, w_out, b_out (all fp32).
// ---------------------------------------------------------------------------
extern "C" void kernel_launch(void* const* d_in, const int* in_sizes, int n_in,
                              void* d_out, int out_size)
{
    (void)in_sizes; (void)n_in; (void)out_size;
    const float* x     = (const float*)d_in[0];
    const float* w_qkv = (const float*)d_in[1];
    const float* b_qkv = (const float*)d_in[2];
    const float* w_out = (const float*)d_in[3];
    const float* b_out = (const float*)d_in[4];
    float* out = (float*)d_out;

    float* qkv_buf  = nullptr;
    float* attn_buf = nullptr;
    cudaGetSymbolAddress((void**)&qkv_buf, g_qkv);
    cudaGetSymbolAddress((void**)&attn_buf, g_attn);

    // 1) QKV projection: [4096,1024] @ [1024,3072] + b
    gemm_tf32_bias_kernel<N_TOK, 3 * D_MODEL, D_MODEL>
        <<<dim3((3 * D_MODEL) / 128, N_TOK / 128), 128>>>(x, w_qkv, b_qkv, qkv_buf);

    // 2) causal flash attention -> [B, T, H*DH]
    flash_attn_kernel<<<dim3(T_SEQ / 64, N_HEADS, B_SZ), 256>>>();

    // 3) output projection: [4096,1024] @ [1024,1024] + b
    gemm_tf32_bias_kernel<N_TOK, D_MODEL, D_MODEL>
        <<<dim3(D_MODEL / 128, N_TOK / 128), 128>>>(attn_buf, w_out, b_out, out);
}

// round 5
// speedup vs baseline: 3.4409x; 2.1577x over previous
#include <cuda_runtime.h>
#include <cstdint>

#define T_SEQ   2048
#define D_MODEL 1024
#define N_HEADS 16
#define D_HEAD  64
#define B_SZ    2
#define N_TOK   (B_SZ * T_SEQ)   // 4096

// Scratch (device globals: allocation-free per harness rules)
__device__ float g_qkv[(size_t)N_TOK * 3 * D_MODEL];   // [4096, 3072]
__device__ float g_attn[(size_t)N_TOK * D_MODEL];      // [4096, 1024]

// ---------------------------------------------------------------------------
// tf32 helpers
// ---------------------------------------------------------------------------
__device__ __forceinline__ uint32_t f2tf32(float x) {
    uint32_t r;
    asm("cvt.rna.tf32.f32 %0, %1;" : "=r"(r) : "f"(x));
    return r;
}

__device__ __forceinline__ void mma_tf32(float c[4], const uint32_t a[4], const uint32_t b[2]) {
    asm volatile(
        "mma.sync.aligned.m16n8k8.row.col.f32.tf32.tf32.f32 "
        "{%0,%1,%2,%3}, {%4,%5,%6,%7}, {%8,%9}, {%0,%1,%2,%3};\n"
        : "+f"(c[0]), "+f"(c[1]), "+f"(c[2]), "+f"(c[3])
        : "r"(a[0]), "r"(a[1]), "r"(a[2]), "r"(a[3]), "r"(b[0]), "r"(b[1]));
}

// ---------------------------------------------------------------------------
// tf32 tensor-core GEMM with fused bias (unchanged from round 3).
// ---------------------------------------------------------------------------
#define LDA 20
#define LDB 136

template <int M, int N, int K>
__global__ void __launch_bounds__(128, 2) gemm_tf32_bias_kernel(
    const float* __restrict__ A, const float* __restrict__ B,
    const float* __restrict__ bias, float* __restrict__ C)
{
    __shared__ uint32_t As[128 * LDA];
    __shared__ uint32_t Bs[16 * LDB];

    const int tid  = threadIdx.x;
    const int warp = tid >> 5;
    const int lane = tid & 31;
    const int g    = lane >> 2;
    const int tg   = lane & 3;
    const int wm   = (warp >> 1) * 64;
    const int wn   = (warp & 1) * 64;

    const int bm = blockIdx.y;
    const int bn = blockIdx.x;

    const float* Ab = A + (size_t)bm * 128 * K;
    const float* Bb = B + (size_t)bn * 128;

    float acc[4][8][4];
    #pragma unroll
    for (int i = 0; i < 4; ++i)
        #pragma unroll
        for (int j = 0; j < 8; ++j)
            #pragma unroll
            for (int q = 0; q < 4; ++q) acc[i][j][q] = 0.0f;

    for (int kt = 0; kt < K; kt += 16) {
        float4 areg[4], breg[4];
        #pragma unroll
        for (int p = 0; p < 4; ++p) {
            int f  = tid + p * 128;
            int ar = f >> 2, ac = (f & 3) * 4;
            areg[p] = *(const float4*)(Ab + (size_t)ar * K + kt + ac);
            int br = f >> 5, bc = (f & 31) * 4;
            breg[p] = *(const float4*)(Bb + (size_t)(kt + br) * N + bc);
        }

        __syncthreads();

        #pragma unroll
        for (int p = 0; p < 4; ++p) {
            int f  = tid + p * 128;
            int ar = f >> 2, ac = (f & 3) * 4;
            uint4 av = make_uint4(f2tf32(areg[p].x), f2tf32(areg[p].y),
                                  f2tf32(areg[p].z), f2tf32(areg[p].w));
            *(uint4*)(As + ar * LDA + ac) = av;
            int br = f >> 5, bc = (f & 31) * 4;
            uint4 bv = make_uint4(f2tf32(breg[p].x), f2tf32(breg[p].y),
                                  f2tf32(breg[p].z), f2tf32(breg[p].w));
            *(uint4*)(Bs + br * LDB + bc) = bv;
        }
        __syncthreads();

        #pragma unroll
        for (int ks = 0; ks < 2; ++ks) {
            const int kk = ks * 8;
            uint32_t a[4][4], b[8][2];
            #pragma unroll
            for (int mm = 0; mm < 4; ++mm) {
                const int r0 = wm + mm * 16;
                a[mm][0] = As[(r0 + g)     * LDA + kk + tg];
                a[mm][1] = As[(r0 + g + 8) * LDA + kk + tg];
                a[mm][2] = As[(r0 + g)     * LDA + kk + tg + 4];
                a[mm][3] = As[(r0 + g + 8) * LDA + kk + tg + 4];
            }
            #pragma unroll
            for (int nn = 0; nn < 8; ++nn) {
                const int c0 = wn + nn * 8 + g;
                b[nn][0] = Bs[(kk + tg)     * LDB + c0];
                b[nn][1] = Bs[(kk + tg + 4) * LDB + c0];
            }
            #pragma unroll
            for (int mm = 0; mm < 4; ++mm)
                #pragma unroll
                for (int nn = 0; nn < 8; ++nn)
                    mma_tf32(acc[mm][nn], a[mm], b[nn]);
        }
    }

    #pragma unroll
    for (int mm = 0; mm < 4; ++mm) {
        const int r0 = bm * 128 + wm + mm * 16 + g;
        #pragma unroll
        for (int nn = 0; nn < 8; ++nn) {
            const int c0g = bn * 128 + wn + nn * 8 + 2 * tg;
            float b0 = bias[c0g], b1 = bias[c0g + 1];
            float2 v0 = make_float2(acc[mm][nn][0] + b0, acc[mm][nn][1] + b1);
            float2 v1 = make_float2(acc[mm][nn][2] + b0, acc[mm][nn][3] + b1);
            *(float2*)(C + (size_t)r0 * N + c0g)       = v0;
            *(float2*)(C + (size_t)(r0 + 8) * N + c0g) = v1;
        }
    }
}

// ---------------------------------------------------------------------------
// Causal flash attention on tf32 tensor cores.
// 128 threads = 4 warps. Q-tile 64 (16 rows/warp), K-tile 64, DH=64.
// Per warp: S(16x64) = Q16x64 @ K^T, online softmax (warp-local rows),
// O(16x64) += P @ V. P re-fragmented via per-warp smem bounce aliased on KP.
// NOTE: tile copy loops are p<8 (128 threads x 8 = 1024 float4 = full 64x64).
// ---------------------------------------------------------------------------
__global__ void __launch_bounds__(128, 2) flash_attn_tc_kernel()
{
    __shared__ uint32_t KP[64 * 68];   // K tile / Q staging / P bounce (aliased)
    __shared__ uint32_t Vs[64 * 72];   // V tile

    const int tid  = threadIdx.x;
    const int warp = tid >> 5;
    const int lane = tid & 31;
    const int g    = lane >> 2;     // 0..7
    const int tg   = lane & 3;      // 0..3
    const int qt   = gridDim.x - 1 - blockIdx.x;   // long diagonals first
    const int h    = blockIdx.y;
    const int b    = blockIdx.z;
    const int q0   = qt * 64;
    const int qrow = warp * 16;     // warp's row offset within Q tile

    const float* qkv = g_qkv;

    // ---- stage Q (64x64) into KP as tf32, extract persistent A-fragments ----
    #pragma unroll
    for (int p = 0; p < 8; ++p) {
        int idx = tid + p * 128;          // 0..1023 float4 slots
        int r = idx >> 4, c = (idx & 15) * 4;
        float4 v = *(const float4*)(qkv + (size_t)(b * T_SEQ + q0 + r) * 3072 + h * 64 + c);
        *(uint4*)(KP + r * 68 + c) =
            make_uint4(f2tf32(v.x), f2tf32(v.y), f2tf32(v.z), f2tf32(v.w));
    }
    __syncthreads();

    uint32_t aq[8][4];
    #pragma unroll
    for (int d0 = 0; d0 < 8; ++d0) {
        aq[d0][0] = KP[(qrow + g)     * 68 + d0 * 8 + tg];
        aq[d0][1] = KP[(qrow + g + 8) * 68 + d0 * 8 + tg];
        aq[d0][2] = KP[(qrow + g)     * 68 + d0 * 8 + tg + 4];
        aq[d0][3] = KP[(qrow + g + 8) * 68 + d0 * 8 + tg + 4];
    }

    float oacc[8][4];
    #pragma unroll
    for (int i = 0; i < 8; ++i)
        #pragma unroll
        for (int j = 0; j < 4; ++j) oacc[i][j] = 0.0f;
    float mrow0 = -1e30f, mrow1 = -1e30f;
    float lrow0 = 0.0f,   lrow1 = 0.0f;

    const int nkt = qt + 1;
    for (int kt = 0; kt < nkt; ++kt) {
        const int k0 = kt * 64;

        __syncthreads();   // prior-iteration K/P and V reads complete

        // ---- load K, V tiles (64x64 each) as tf32 ----
        #pragma unroll
        for (int p = 0; p < 8; ++p) {
            int idx = tid + p * 128;      // 0..1023 float4 slots
            int r = idx >> 4, c = (idx & 15) * 4;
            const float* base = qkv + (size_t)(b * T_SEQ + k0 + r) * 3072 + h * 64 + c;
            float4 kv = *(const float4*)(base + 1024);
            float4 vv = *(const float4*)(base + 2048);
            *(uint4*)(KP + r * 68 + c) =
                make_uint4(f2tf32(kv.x), f2tf32(kv.y), f2tf32(kv.z), f2tf32(kv.w));
            *(uint4*)(Vs + r * 72 + c) =
                make_uint4(f2tf32(vv.x), f2tf32(vv.y), f2tf32(vv.z), f2tf32(vv.w));
        }
        __syncthreads();

        // ---- S = Q @ K^T  (per warp: 16x64) ----
        float sacc[8][4];
        #pragma unroll
        for (int i = 0; i < 8; ++i)
            #pragma unroll
            for (int j = 0; j < 4; ++j) sacc[i][j] = 0.0f;

        #pragma unroll
        for (int n0 = 0; n0 < 8; ++n0) {
            #pragma unroll
            for (int d0 = 0; d0 < 8; ++d0) {
                uint32_t bf[2] = { KP[(n0 * 8 + g) * 68 + d0 * 8 + tg],
                                   KP[(n0 * 8 + g) * 68 + d0 * 8 + tg + 4] };
                mma_tf32(sacc[n0], aq[d0], bf);
            }
        }

        // ---- scale + causal mask + row max ----
        const int row0 = q0 + qrow + g;
        const int row1 = row0 + 8;
        const bool domask = (k0 + 63 > q0 + qrow);
        float ml0 = -1e30f, ml1 = -1e30f;
        #pragma unroll
        for (int n0 = 0; n0 < 8; ++n0) {
            const int c0 = k0 + n0 * 8 + 2 * tg;
            const int c1 = c0 + 1;
            float s0 = sacc[n0][0] * 0.125f;
            float s1 = sacc[n0][1] * 0.125f;
            float s2 = sacc[n0][2] * 0.125f;
            float s3 = sacc[n0][3] * 0.125f;
            if (domask) {
                if (c0 > row0) s0 = -1e30f;
                if (c1 > row0) s1 = -1e30f;
                if (c0 > row1) s2 = -1e30f;
                if (c1 > row1) s3 = -1e30f;
            }
            sacc[n0][0] = s0; sacc[n0][1] = s1;
            sacc[n0][2] = s2; sacc[n0][3] = s3;
            ml0 = fmaxf(ml0, fmaxf(s0, s1));
            ml1 = fmaxf(ml1, fmaxf(s2, s3));
        }
        ml0 = fmaxf(ml0, __shfl_xor_sync(0xffffffffu, ml0, 1));
        ml0 = fmaxf(ml0, __shfl_xor_sync(0xffffffffu, ml0, 2));
        ml1 = fmaxf(ml1, __shfl_xor_sync(0xffffffffu, ml1, 1));
        ml1 = fmaxf(ml1, __shfl_xor_sync(0xffffffffu, ml1, 2));

        const float nm0 = fmaxf(mrow0, ml0);
        const float nm1 = fmaxf(mrow1, ml1);
        const float al0 = __expf(mrow0 - nm0);
        const float al1 = __expf(mrow1 - nm1);
        mrow0 = nm0; mrow1 = nm1;

        // ---- P = exp(S - m), row sums ----
        float sum0 = 0.0f, sum1 = 0.0f;
        #pragma unroll
        for (int n0 = 0; n0 < 8; ++n0) {
            float p0 = __expf(sacc[n0][0] - nm0);
            float p1 = __expf(sacc[n0][1] - nm0);
            float p2 = __expf(sacc[n0][2] - nm1);
            float p3 = __expf(sacc[n0][3] - nm1);
            sacc[n0][0] = p0; sacc[n0][1] = p1;
            sacc[n0][2] = p2; sacc[n0][3] = p3;
            sum0 += p0 + p1;
            sum1 += p2 + p3;
        }
        sum0 += __shfl_xor_sync(0xffffffffu, sum0, 1);
        sum0 += __shfl_xor_sync(0xffffffffu, sum0, 2);
        sum1 += __shfl_xor_sync(0xffffffffu, sum1, 1);
        sum1 += __shfl_xor_sync(0xffffffffu, sum1, 2);
        lrow0 = lrow0 * al0 + sum0;
        lrow1 = lrow1 * al1 + sum1;

        #pragma unroll
        for (int n0 = 0; n0 < 8; ++n0) {
            oacc[n0][0] *= al0; oacc[n0][1] *= al0;
            oacc[n0][2] *= al1; oacc[n0][3] *= al1;
        }

        // ---- bounce P through smem (C-frag layout -> A-frag layout) ----
        __syncthreads();   // ALL warps done reading K region before P overwrite
        #pragma unroll
        for (int n0 = 0; n0 < 8; ++n0) {
            *(uint2*)(KP + (qrow + g)     * 68 + n0 * 8 + 2 * tg) =
                make_uint2(f2tf32(sacc[n0][0]), f2tf32(sacc[n0][1]));
            *(uint2*)(KP + (qrow + g + 8) * 68 + n0 * 8 + 2 * tg) =
                make_uint2(f2tf32(sacc[n0][2]), f2tf32(sacc[n0][3]));
        }
        __syncwarp();

        uint32_t ap[8][4];
        #pragma unroll
        for (int kc = 0; kc < 8; ++kc) {
            ap[kc][0] = KP[(qrow + g)     * 68 + kc * 8 + tg];
            ap[kc][1] = KP[(qrow + g + 8) * 68 + kc * 8 + tg];
            ap[kc][2] = KP[(qrow + g)     * 68 + kc * 8 + tg + 4];
            ap[kc][3] = KP[(qrow + g + 8) * 68 + kc * 8 + tg + 4];
        }

        // ---- O += P @ V ----
        #pragma unroll
        for (int n0 = 0; n0 < 8; ++n0) {
            #pragma unroll
            for (int kc = 0; kc < 8; ++kc) {
                uint32_t bf[2] = { Vs[(kc * 8 + tg)     * 72 + n0 * 8 + g],
                                   Vs[(kc * 8 + tg + 4) * 72 + n0 * 8 + g] };
                mma_tf32(oacc[n0], ap[kc], bf);
            }
        }
    }

    // ---- epilogue: normalize, write [B*T, D_MODEL] ----
    const float li0 = 1.0f / lrow0;
    const float li1 = 1.0f / lrow1;
    const size_t grow0 = (size_t)(b * T_SEQ + q0 + qrow + g);
    const size_t grow1 = grow0 + 8;
    #pragma unroll
    for (int n0 = 0; n0 < 8; ++n0) {
        const int col = h * 64 + n0 * 8 + 2 * tg;
        *(float2*)(g_attn + grow0 * D_MODEL + col) =
            make_float2(oacc[n0][0] * li0, oacc[n0][1] * li0);
        *(float2*)(g_attn + grow1 * D_MODEL + col) =
            make_float2(oacc[n0][2] * li1, oacc[n0][3] * li1);
    }
}

// ---------------------------------------------------------------------------
// Harness entry. Inputs: x, w_qkv, b_qkv, w_out, b_out (all fp32).
// ---------------------------------------------------------------------------
extern "C" void kernel_launch(void* const* d_in, const int* in_sizes, int n_in,
                              void* d_out, int out_size)
{
    (void)in_sizes; (void)n_in; (void)out_size;
    const float* x     = (const float*)d_in[0];
    const float* w_qkv = (const float*)d_in[1];
    const float* b_qkv = (const float*)d_in[2];
    const float* w_out = (const float*)d_in[3];
    const float* b_out = (const float*)d_in[4];
    float* out = (float*)d_out;

    float* qkv_buf  = nullptr;
    float* attn_buf = nullptr;
    cudaGetSymbolAddress((void**)&qkv_buf, g_qkv);
    cudaGetSymbolAddress((void**)&attn_buf, g_attn);

    // 1) QKV projection: [4096,1024] @ [1024,3072] + b
    gemm_tf32_bias_kernel<N_TOK, 3 * D_MODEL, D_MODEL>
        <<<dim3((3 * D_MODEL) / 128, N_TOK / 128), 128>>>(x, w_qkv, b_qkv, qkv_buf);

    // 2) causal flash attention (tensor cores) -> [B, T, H*DH]
    flash_attn_tc_kernel<<<dim3(T_SEQ / 64, N_HEADS, B_SZ), 128>>>();

    // 3) output projection: [4096,1024] @ [1024,1024] + b
    gemm_tf32_bias_kernel<N_TOK, D_MODEL, D_MODEL>
        <<<dim3(D_MODEL / 128, N_TOK / 128), 128>>>(attn_buf, w_out, b_out, out);
}